// round 2
// baseline (speedup 1.0000x reference)
#include <cuda_runtime.h>

#define DI    104          // input feature dim
#define DO    144          // conv output dim (incl. gates)
#define SO    120          // final output channels
#define NB    16           // radial basis count
#define NPTS  1024         // N
#define MPTS  1024         // M
#define BATCH 4
#define TN    4            // n-points per CTA
#define CM    32           // m-chunk

typedef unsigned long long ull;

// Transposed W: Wt[k][i][o] (o contiguous) — device scratch, no allocation.
__device__ float g_Wt[NB * DI * DO];

__device__ __forceinline__ ull pack2(float x, float y) {
    ull r;
    asm("mov.b64 %0, {%1, %2};" : "=l"(r) : "f"(x), "f"(y));
    return r;
}
__device__ __forceinline__ void unpack2(ull v, float& x, float& y) {
    asm("mov.b64 {%0, %1}, %2;" : "=f"(x), "=f"(y) : "l"(v));
}
// Packed 2-wide fp32 FMA (sm_103a FFMA2)
__device__ __forceinline__ ull fma2(ull a, ull b, ull c) {
    ull d;
    asm("fma.rn.f32x2 %0, %1, %2, %3;" : "=l"(d) : "l"(a), "l"(b), "l"(c));
    return d;
}

union F4U {
    float4 f;
    ull u[2];
};

__global__ void transposeW(const float* __restrict__ W) {
    int idx = blockIdx.x * blockDim.x + threadIdx.x;
    if (idx < NB * DI * DO) {
        int k = idx / (DI * DO);
        int r = idx % (DI * DO);
        int i = r / DO;
        int o = r % DO;
        g_Wt[idx] = W[(k * DO + o) * DI + i];
    }
}

__global__ __launch_bounds__(128, 4) void se3conv(
    const float* __restrict__ feat,   // [B, DI, M]
    const float* __restrict__ diff,   // [B, N, M, 3]
    const float* __restrict__ mask,   // [B, N, M]
    float* __restrict__ out)          // [B, SO, N]
{
    // Phase 1: feat_s [104][33] (3432 f) + phi_s [CM][TN][16] (2048 f) = 5480 f
    // Phase 2: tmp4 [16][104] float4 (6656 f) + y_s [144][4] (576 f) = 7232 f
    __shared__ __align__(16) float smem[7232];
    float*  feat_s = smem;                 // pitch 33 (conflict-free)
    float*  phi_s  = smem + DI * 33;       // k-contiguous
    float4* tmp4   = (float4*)smem;        // [k*DI + i] -> (n0,n1,n2,n3)
    float*  y_s    = smem + NB * DI * 4;   // [o][n]

    const int tid = threadIdx.x;
    const int b   = blockIdx.x >> 8;            // 256 n-tiles per batch
    const int n0  = (blockIdx.x & 255) * TN;

    // acc[n][q] packs (k=2q, k=2q+1) fp32 pair
    ull acc[TN][8];
#pragma unroll
    for (int n = 0; n < TN; n++)
#pragma unroll
        for (int q = 0; q < 8; q++) acc[n][q] = 0ull;

    const int pn = tid >> 5;   // n within tile (phi producer)
    const int pm = tid & 31;   // m within chunk
    const float* diff_p = diff + ((size_t)(b * NPTS + n0 + pn)) * MPTS * 3;
    const float* mask_p = mask + ((size_t)(b * NPTS + n0 + pn)) * MPTS;
    const float* feat_p = feat + (size_t)b * DI * MPTS;

    for (int mc = 0; mc < MPTS; mc += CM) {
        __syncthreads();   // previous chunk fully consumed

        // --- stage features chunk [104][32] (coalesced, padded pitch 33) ---
#pragma unroll
        for (int idx = tid; idx < DI * CM; idx += 128) {
            int ii = idx >> 5, mm = idx & 31;
            feat_s[ii * 33 + mm] = feat_p[ii * MPTS + mc + mm];
        }

        // --- phi for this thread's (n,m) pair: 16 masked gaussians ---
        {
            int gm = mc + pm;
            float dx = diff_p[gm * 3 + 0];
            float dy = diff_p[gm * 3 + 1];
            float dz = diff_p[gm * 3 + 2];
            float msk = mask_p[gm];
            float r = sqrtf(fmaf(dx, dx, fmaf(dy, dy, fmaf(dz, dz, 1e-12f))));
            float4* dst = (float4*)(phi_s + (pm * TN + pn) * 16);
#pragma unroll
            for (int q = 0; q < 4; q++) {
                float4 v;
                float d0 = r - (float)(4 * q + 0) * (2.0f / 15.0f);
                float d1 = r - (float)(4 * q + 1) * (2.0f / 15.0f);
                float d2 = r - (float)(4 * q + 2) * (2.0f / 15.0f);
                float d3 = r - (float)(4 * q + 3) * (2.0f / 15.0f);
                v.x = __expf(-16.0f * d0 * d0) * msk;
                v.y = __expf(-16.0f * d1 * d1) * msk;
                v.z = __expf(-16.0f * d2 * d2) * msk;
                v.w = __expf(-16.0f * d3 * d3) * msk;
                dst[q] = v;
            }
        }
        __syncthreads();

        // --- accumulate tmp[n][k] += phi[n][m][k] * feat[i][m] ---
        if (tid < DI) {
#pragma unroll 2
            for (int m = 0; m < CM; m++) {
                float f = feat_s[tid * 33 + m];
                ull ff = pack2(f, f);
                const float4* pp = (const float4*)phi_s + m * TN * 4;
#pragma unroll
                for (int n = 0; n < TN; n++) {
#pragma unroll
                    for (int q = 0; q < 4; q++) {
                        F4U p;
                        p.f = pp[n * 4 + q];            // broadcast LDS.128
                        acc[n][2 * q]     = fma2(p.u[0], ff, acc[n][2 * q]);
                        acc[n][2 * q + 1] = fma2(p.u[1], ff, acc[n][2 * q + 1]);
                    }
                }
            }
        }
    }

    // --- spill tmp to smem as [k][i] -> float4 over n ---
    __syncthreads();
    if (tid < DI) {
#pragma unroll
        for (int q = 0; q < 8; q++) {
            float a0, a1, b0, b1, c0, c1, d0, d1;
            unpack2(acc[0][q], a0, a1);
            unpack2(acc[1][q], b0, b1);
            unpack2(acc[2][q], c0, c1);
            unpack2(acc[3][q], d0, d1);
            tmp4[(2 * q)     * DI + tid] = make_float4(a0, b0, c0, d0);  // k=2q
            tmp4[(2 * q + 1) * DI + tid] = make_float4(a1, b1, c1, d1);  // k=2q+1
        }
    }
    __syncthreads();

    // --- stage B: y[o][n] = sum_{k,i} tmp[n][k][i] * Wt[k][i][o] ---
    {
        const int o = tid;                 // 0..127
        const bool has2 = (tid < (DO - 128));
        const int o2 = tid + 128;          // 128..143 for tid<16
        ull y0 = 0ull, y1 = 0ull, z0 = 0ull, z1 = 0ull;

        for (int k = 0; k < NB; k++) {
            const float* wrow = g_Wt + k * DI * DO;
            const float4* trow = tmp4 + k * DI;
#pragma unroll 4
            for (int i2 = 0; i2 < DI; i2++) {
                F4U t;
                t.f = trow[i2];                       // broadcast LDS.128
                float w = wrow[i2 * DO + o];          // coalesced LDG
                ull ww = pack2(w, w);
                y0 = fma2(t.u[0], ww, y0);
                y1 = fma2(t.u[1], ww, y1);
                if (has2) {
                    float w2 = wrow[i2 * DO + o2];
                    ull ww2 = pack2(w2, w2);
                    z0 = fma2(t.u[0], ww2, z0);
                    z1 = fma2(t.u[1], ww2, z1);
                }
            }
        }
        float a, b2, c, d;
        unpack2(y0, a, b2);
        unpack2(y1, c, d);
        ((float4*)y_s)[o] = make_float4(a, b2, c, d);
        if (has2) {
            unpack2(z0, a, b2);
            unpack2(z1, c, d);
            ((float4*)y_s)[o2] = make_float4(a, b2, c, d);
        }
    }
    __syncthreads();

    // --- gating epilogue ---
    for (int idx = tid; idx < SO * TN; idx += 128) {
        int c = idx >> 2;
        int n = idx & 3;
        float v = y_s[c * 4 + n];
        float res;
        if (c < 32) {
            res = fmaxf(v, 0.0f);                       // scalar relu
        } else if (c < 80) {
            int j = (c - 32) / 3;                       // l=1 gates: y[120+j]
            float g = y_s[(120 + j) * 4 + n];
            res = v * __fdividef(1.0f, 1.0f + __expf(-g));
        } else {
            int j = (c - 80) / 5;                       // l=2 gates: y[136+j]
            float g = y_s[(136 + j) * 4 + n];
            res = v * __fdividef(1.0f, 1.0f + __expf(-g));
        }
        out[((size_t)b * SO + c) * NPTS + n0 + n] = res;
    }
}

extern "C" void kernel_launch(void* const* d_in, const int* in_sizes, int n_in,
                              void* d_out, int out_size) {
    (void)in_sizes; (void)n_in; (void)out_size;
    const float* feat = (const float*)d_in[0];
    const float* diff = (const float*)d_in[1];
    const float* mask = (const float*)d_in[2];
    const float* W    = (const float*)d_in[3];

    transposeW<<<(NB * DI * DO + 255) / 256, 256>>>(W);
    se3conv<<<BATCH * (NPTS / TN), 128>>>(feat, diff, mask, (float*)d_out);
}

// round 3
// speedup vs baseline: 1.2012x; 1.2012x over previous
#include <cuda_runtime.h>
#include <math.h>

#define DI    104          // input feature dim
#define DO    144          // conv output dim (incl. gates)
#define SO    120          // final output channels
#define NB    16           // radial basis count
#define NPTS  1024
#define MPTS  1024
#define BATCH 4
#define TN    8            // n-points per CTA
#define CM    32           // m-chunk
#define THREADS 256

typedef unsigned long long ull;

// Transposed W: Wt[k][i][o] (o contiguous)
__device__ float g_Wt[NB * DI * DO];
// chain constants C_k = exp((64/225)*(2k-1)), k=1..15
__device__ float g_cs[16];

__device__ __forceinline__ ull pack2(float x, float y) {
    ull r; asm("mov.b64 %0, {%1, %2};" : "=l"(r) : "f"(x), "f"(y)); return r;
}
__device__ __forceinline__ void unpack2(ull v, float& x, float& y) {
    asm("mov.b64 {%0, %1}, %2;" : "=f"(x), "=f"(y) : "l"(v));
}
__device__ __forceinline__ ull fma2(ull a, ull b, ull c) {
    ull d; asm("fma.rn.f32x2 %0, %1, %2, %3;" : "=l"(d) : "l"(a), "l"(b), "l"(c));
    return d;
}

union F4U { float4 f; ull u[2]; };

__global__ void initConsts() {
    int k = threadIdx.x;
    if (k < 16) g_cs[k] = (float)exp((64.0 / 225.0) * (2.0 * k - 1.0));
}

__global__ void transposeW(const float* __restrict__ W) {
    int idx = blockIdx.x * blockDim.x + threadIdx.x;
    if (idx < NB * DI * DO) {
        int k = idx / (DI * DO);
        int r = idx % (DI * DO);
        int i = r / DO;
        int o = r % DO;
        g_Wt[idx] = W[(k * DO + o) * DI + i];
    }
}

// smem layout (floats):
//  phase 1: feat_s [104][33] = 3432 | phi_s [32m][8n][16k] = 4096  (union base)
//  phase 2: tmp  [16k][104i][8n] = 13312 | y_s [144][8] = 1152  -> 14464
//  cs_s at 14464 (alive phase 1 only; y_s ends exactly at 14464)
#define SMEM_FLOATS 14480

__global__ __launch_bounds__(THREADS, 2) void se3conv(
    const float* __restrict__ feat,   // [B, DI, M]
    const float* __restrict__ diff,   // [B, N, M, 3]
    const float* __restrict__ mask,   // [B, N, M]
    float* __restrict__ out)          // [B, SO, N]
{
    extern __shared__ __align__(16) float smem[];
    float*  feat_s = smem;                  // pitch 33
    float*  phi_s  = smem + DI * 33;        // [m][n8][16]
    float*  cs_s   = smem + 14464;
    float4* tmp4   = (float4*)smem;         // [(k*DI+i)*2 + g]
    float*  y_s    = smem + NB * DI * TN;   // [o][8]

    const int tid  = threadIdx.x;
    const int b    = blockIdx.x >> 7;            // 128 n-tiles per batch
    const int n0   = (blockIdx.x & 127) * TN;
    const int gi   = tid >> 7;                   // i-group (n-half)
    const int li   = tid & 127;                  // i lane

    if (tid < 16) cs_s[tid] = g_cs[tid];

    ull acc[4][8];
#pragma unroll
    for (int n = 0; n < 4; n++)
#pragma unroll
        for (int q = 0; q < 8; q++) acc[n][q] = 0ull;

    const int pn = tid >> 5;   // 0..7 : n for phi production
    const int pm = tid & 31;   // m within chunk
    const float* diff_p = diff + ((size_t)(b * NPTS + n0 + pn)) * MPTS * 3;
    const float* mask_p = mask + ((size_t)(b * NPTS + n0 + pn)) * MPTS;
    const float* feat_p = feat + (size_t)b * DI * MPTS;

    __syncthreads();   // cs_s visible

    for (int mc = 0; mc < MPTS; mc += CM) {
        // --- stage features [104][32], coalesced, pitch 33 ---
#pragma unroll
        for (int idx = tid; idx < DI * CM; idx += THREADS) {
            int ii = idx >> 5, mm = idx & 31;
            feat_s[ii * 33 + mm] = feat_p[ii * MPTS + mc + mm];
        }

        // --- phi for this thread's (n,m): 2 EX2 + chain instead of 16 EX2 ---
        {
            int gm = mc + pm;
            float dx = diff_p[gm * 3 + 0];
            float dy = diff_p[gm * 3 + 1];
            float dz = diff_p[gm * 3 + 2];
            float msk = mask_p[gm];
            float r2 = fmaf(dx, dx, fmaf(dy, dy, fmaf(dz, dz, 1e-12f)));
            float r  = r2 * rsqrtf(r2);
            float d15 = r - 2.0f;
            float p = __expf(-16.0f * d15 * d15) * msk;    // phi_15 * mask
            float w = __expf(-4.2666667f * r);             // exp(-32*delta*r)
            float ph[16];
            ph[15] = p;
#pragma unroll
            for (int k = 15; k >= 1; k--) {
                p = p * (w * cs_s[k]);
                ph[k - 1] = p;
            }
            float4* dst = (float4*)(phi_s + (pm * TN + pn) * 16);
#pragma unroll
            for (int q = 0; q < 4; q++)
                dst[q] = make_float4(ph[4 * q], ph[4 * q + 1], ph[4 * q + 2], ph[4 * q + 3]);
        }
        __syncthreads();

        // --- tmp[n][k] += phi[n][m][k] * feat[i][m] (FFMA2) ---
        if (li < DI) {
#pragma unroll 2
            for (int m = 0; m < CM; m++) {
                float f = feat_s[li * 33 + m];
                ull ff = pack2(f, f);
                const float4* pp = (const float4*)phi_s + (m * TN + gi * 4) * 4;
#pragma unroll
                for (int n = 0; n < 4; n++) {
#pragma unroll
                    for (int q = 0; q < 4; q++) {
                        F4U p; p.f = pp[n * 4 + q];
                        acc[n][2 * q]     = fma2(p.u[0], ff, acc[n][2 * q]);
                        acc[n][2 * q + 1] = fma2(p.u[1], ff, acc[n][2 * q + 1]);
                    }
                }
            }
        }
        __syncthreads();   // chunk consumed before restaging
    }

    // --- spill tmp to smem: [k][i] -> 2x float4 over 8 n ---
    if (li < DI) {
#pragma unroll
        for (int q = 0; q < 8; q++) {
            float a0, a1, b0, b1, c0, c1, d0, d1;
            unpack2(acc[0][q], a0, a1);
            unpack2(acc[1][q], b0, b1);
            unpack2(acc[2][q], c0, c1);
            unpack2(acc[3][q], d0, d1);
            tmp4[((2 * q)     * DI + li) * 2 + gi] = make_float4(a0, b0, c0, d0);
            tmp4[((2 * q + 1) * DI + li) * 2 + gi] = make_float4(a1, b1, c1, d1);
        }
    }
    __syncthreads();

    // --- stage B: y[o][n] = sum_{k,i} tmp[k][i][n] * Wt[k][i][o] ---
    if (tid < DO) {
        const int o = tid;
        ull y0 = 0ull, y1 = 0ull, y2 = 0ull, y3 = 0ull;
        for (int k = 0; k < NB; k++) {
            const float*  wrow = g_Wt + k * DI * DO;
            const float4* trow = tmp4 + k * DI * 2;
#pragma unroll 4
            for (int i2 = 0; i2 < DI; i2++) {
                F4U t0, t1;
                t0.f = trow[i2 * 2 + 0];
                t1.f = trow[i2 * 2 + 1];
                float wv = wrow[i2 * DO + o];
                ull ww = pack2(wv, wv);
                y0 = fma2(t0.u[0], ww, y0);
                y1 = fma2(t0.u[1], ww, y1);
                y2 = fma2(t1.u[0], ww, y2);
                y3 = fma2(t1.u[1], ww, y3);
            }
        }
        float a, b2, c, d;
        float4* yd = (float4*)(y_s + o * TN);
        unpack2(y0, a, b2); unpack2(y1, c, d);
        yd[0] = make_float4(a, b2, c, d);
        unpack2(y2, a, b2); unpack2(y3, c, d);
        yd[1] = make_float4(a, b2, c, d);
    }
    __syncthreads();

    // --- gating epilogue ---
    for (int idx = tid; idx < SO * TN; idx += THREADS) {
        int c = idx >> 3;
        int n = idx & 7;
        float v = y_s[c * TN + n];
        float res;
        if (c < 32) {
            res = fmaxf(v, 0.0f);
        } else if (c < 80) {
            int j = (c - 32) / 3;
            float g = y_s[(120 + j) * TN + n];
            res = v * __fdividef(1.0f, 1.0f + __expf(-g));
        } else {
            int j = (c - 80) / 5;
            float g = y_s[(136 + j) * TN + n];
            res = v * __fdividef(1.0f, 1.0f + __expf(-g));
        }
        out[((size_t)b * SO + c) * NPTS + n0 + n] = res;
    }
}

extern "C" void kernel_launch(void* const* d_in, const int* in_sizes, int n_in,
                              void* d_out, int out_size) {
    (void)in_sizes; (void)n_in; (void)out_size;
    const float* feat = (const float*)d_in[0];
    const float* diff = (const float*)d_in[1];
    const float* mask = (const float*)d_in[2];
    const float* W    = (const float*)d_in[3];

    cudaFuncSetAttribute(se3conv, cudaFuncAttributeMaxDynamicSharedMemorySize,
                         SMEM_FLOATS * sizeof(float));

    initConsts<<<1, 16>>>();
    transposeW<<<(NB * DI * DO + 255) / 256, 256>>>(W);
    se3conv<<<BATCH * (NPTS / TN), THREADS, SMEM_FLOATS * sizeof(float)>>>(
        feat, diff, mask, (float*)d_out);
}